// round 1
// baseline (speedup 1.0000x reference)
#include <cuda_runtime.h>

#define T_STEPS 65536
#define INPUT   99
#define HIDDEN  64
#define GATES   256   // 4*HIDDEN
#define TS      16    // timesteps per block in the precompute kernel

// Scratch for precomputed input projections, packed as float2 per (t, j):
//   g_xz[(t*128 + j)*2 + 0] = xz[t][j]        (row j     : i-gate for j<64, f-gate for 64<=j<128)
//   g_xz[(t*128 + j)*2 + 1] = xz[t][j + 128]  (row j+128 : g-gate for j<64, o-gate for 64<=j<128)
// +8 steps of padding so the prefetch ring can read past the end harmlessly.
__device__ float g_xz[(T_STEPS + 8) * GATES];

typedef unsigned long long ull;

// ---------------- packed f32x2 helpers (Blackwell double-rate fp32) ----------------
__device__ __forceinline__ ull fma2(ull a, ull b, ull c) {
    ull d;
    asm("fma.rn.f32x2 %0, %1, %2, %3;" : "=l"(d) : "l"(a), "l"(b), "l"(c));
    return d;
}
__device__ __forceinline__ ull add2(ull a, ull b) {
    ull d;
    asm("add.rn.f32x2 %0, %1, %2;" : "=l"(d) : "l"(a), "l"(b));
    return d;
}
__device__ __forceinline__ float lo32(ull v) { return __uint_as_float((unsigned)v); }
__device__ __forceinline__ float hi32(ull v) { return __uint_as_float((unsigned)(v >> 32)); }

// ---------------- fast-but-accurate transcendentals (MUFU, err ~1e-7) ----------------
__device__ __forceinline__ float fast_ex2(float x) {
    float y; asm("ex2.approx.f32 %0, %1;" : "=f"(y) : "f"(x)); return y;
}
__device__ __forceinline__ float fast_rcp(float x) {
    float y; asm("rcp.approx.f32 %0, %1;" : "=f"(y) : "f"(x)); return y;
}
__device__ __forceinline__ float sigmoidf_(float x) {
    return fast_rcp(1.0f + fast_ex2(-1.4426950408889634f * x));
}
__device__ __forceinline__ float tanhf_(float x) {
    // tanh(x) = 2*sigmoid(2x) - 1
    return fmaf(2.0f, fast_rcp(1.0f + fast_ex2(-2.8853900817779268f * x)), -1.0f);
}

// ============================================================================
// Kernel 1: xz[t][g] = sum_d x[t][d] * W_ih[g][d] + b_ih[g] + b_hh[g]
// Block = 256 threads (one per gate row), TS=16 timesteps per block.
// x tile is staged into SMEM transposed to [d][t] so the inner loop reads
// float4 (4 timesteps) per LDS; W_ih row elements come via LDG (L1-resident).
// ============================================================================
__global__ void xz_kernel(const float* __restrict__ x,
                          const float* __restrict__ W_ih,
                          const float* __restrict__ b_ih,
                          const float* __restrict__ b_hh) {
    __shared__ __align__(16) float xs[INPUT * TS];  // [d][t]
    const int tid = threadIdx.x;
    const int t0  = blockIdx.x * TS;

    for (int i = tid; i < TS * INPUT; i += 256) {
        int t = i / INPUT;
        int d = i - t * INPUT;
        xs[d * TS + t] = x[(size_t)(t0 + t) * INPUT + d];
    }
    __syncthreads();

    const int g = tid;
    float bs = b_ih[g] + b_hh[g];
    float acc[TS];
#pragma unroll
    for (int t = 0; t < TS; t++) acc[t] = bs;

    const float* wrow = W_ih + g * INPUT;
#pragma unroll 3
    for (int d = 0; d < INPUT; d++) {
        float w = __ldg(wrow + d);
        const float4* xv = (const float4*)(xs + d * TS);
#pragma unroll
        for (int q = 0; q < TS / 4; q++) {
            float4 v = xv[q];
            acc[q * 4 + 0] = fmaf(w, v.x, acc[q * 4 + 0]);
            acc[q * 4 + 1] = fmaf(w, v.y, acc[q * 4 + 1]);
            acc[q * 4 + 2] = fmaf(w, v.z, acc[q * 4 + 2]);
            acc[q * 4 + 3] = fmaf(w, v.w, acc[q * 4 + 3]);
        }
    }

    // Scatter into the packed layout the scan kernel wants.
    const int jj   = (g < 128) ? g : (g - 128);
    const int comp = (g < 128) ? 0 : 1;
#pragma unroll
    for (int t = 0; t < TS; t++) {
        g_xz[((size_t)(t0 + t) * 128 + jj) * 2 + comp] = acc[t];
    }
}

// ============================================================================
// Kernel 2: persistent single-CTA LSTM scan + MLP head.
// 128 threads. Thread j owns gate rows j and j+128 (W_hh rows in registers,
// packed as f32x2). Per step:
//   - all threads: z = xz[t] (prefetched) + W_hh_rows @ h   (f32x2 FMAs)
//   - threads 64..127: f=sig(zA), o=sig(zB) -> SMEM   } computed in
//   - threads  0..63 : i=sig(zA), g=tanh(zB)          } parallel
//   - bar; threads 0..63: c = f*c + i*g; h = o*tanh(c) -> SMEM; bar
// ============================================================================
__global__ void __launch_bounds__(128, 1)
scan_kernel(const float* __restrict__ Whh,
            const float* __restrict__ W1,
            const float* __restrict__ W2,
            const float* __restrict__ b2v,
            float* __restrict__ out) {
    __shared__ __align__(16) float hsm[HIDDEN];
    __shared__ float fo[128];  // [0..63]=f, [64..127]=o ; reused for head
    const int j = threadIdx.x;

    // W_hh rows j and j+128 as packed f32x2 pairs (k, k+1). Rows are 256B
    // aligned, pairs 8B aligned; little-endian bit pattern == {lo,hi} floats.
    ull wA[32], wB[32];
    const ull* W64 = (const ull*)Whh;
#pragma unroll
    for (int i = 0; i < 32; i++) {
        wA[i] = W64[j * 32 + i];
        wB[i] = W64[(j + 128) * 32 + i];
    }

    if (j < HIDDEN) hsm[j] = 0.0f;
    float c = 0.0f;

    // Depth-4 register ring for xz prefetch (hides ~577-cyc DRAM latency).
    const float2* xzp = ((const float2*)g_xz) + j;
    float2 zb[4];
#pragma unroll
    for (int p = 0; p < 4; p++) zb[p] = xzp[(size_t)p * 128];
    __syncthreads();

    for (int t = 0; t < T_STEPS; t += 4) {
#pragma unroll
        for (int s = 0; s < 4; s++) {
            float2 z = zb[s];
            zb[s] = xzp[(size_t)(t + s + 4) * 128];  // reads <= T+7 (padded)

            // ---- matvec: zA = W_hh[rowA] @ h, zB = W_hh[rowB] @ h ----
            ull a0 = 0, a1 = 0, a2 = 0, a3 = 0;
            ull d0 = 0, d1 = 0, d2 = 0, d3 = 0;
            const ulonglong2* h64 = (const ulonglong2*)hsm;
#pragma unroll
            for (int q = 0; q < 8; q++) {
                ulonglong2 hx = h64[q * 2];      // h pairs 4q+0, 4q+1
                ulonglong2 hy = h64[q * 2 + 1];  // h pairs 4q+2, 4q+3
                a0 = fma2(wA[q * 4 + 0], hx.x, a0);
                a1 = fma2(wA[q * 4 + 1], hx.y, a1);
                a2 = fma2(wA[q * 4 + 2], hy.x, a2);
                a3 = fma2(wA[q * 4 + 3], hy.y, a3);
                d0 = fma2(wB[q * 4 + 0], hx.x, d0);
                d1 = fma2(wB[q * 4 + 1], hx.y, d1);
                d2 = fma2(wB[q * 4 + 2], hy.x, d2);
                d3 = fma2(wB[q * 4 + 3], hy.y, d3);
            }
            a0 = add2(a0, a1); a2 = add2(a2, a3); a0 = add2(a0, a2);
            d0 = add2(d0, d1); d2 = add2(d2, d3); d0 = add2(d0, d2);
            float zA = z.x + lo32(a0) + hi32(a0);
            float zB = z.y + lo32(d0) + hi32(d0);

            // ---- gates, split across warp halves ----
            float ii = 0.0f, gg = 0.0f;
            if (j >= 64) {
                fo[j - 64] = sigmoidf_(zA);  // f for unit j-64
                fo[j]      = sigmoidf_(zB);  // o for unit j-64
            } else {
                ii = sigmoidf_(zA);          // i for unit j
                gg = tanhf_(zB);             // g for unit j
            }
            __syncthreads();
            if (j < 64) {
                float f = fo[j];
                float o = fo[64 + j];
                c = fmaf(f, c, ii * gg);
                hsm[j] = o * tanhf_(c);
            }
            __syncthreads();
        }
    }

    // ---- MLP head: out = W2 @ relu(W1 @ relu(h_T)) + b2 ----
    if (j < 32) {
        float acc = 0.0f;
#pragma unroll
        for (int k = 0; k < 64; k++)
            acc = fmaf(W1[j * 64 + k], fmaxf(hsm[k], 0.0f), acc);
        fo[j] = fmaxf(acc, 0.0f);
    }
    __syncthreads();
    if (j < 3) {
        float acc = b2v[j];
#pragma unroll
        for (int k = 0; k < 32; k++)
            acc = fmaf(W2[j * 32 + k], fo[k], acc);
        out[j] = acc;
    }
}

// ============================================================================
extern "C" void kernel_launch(void* const* d_in, const int* in_sizes, int n_in,
                              void* d_out, int out_size) {
    (void)in_sizes; (void)n_in; (void)out_size;
    const float* x    = (const float*)d_in[0];
    const float* W_ih = (const float*)d_in[1];
    const float* W_hh = (const float*)d_in[2];
    const float* b_ih = (const float*)d_in[3];
    const float* b_hh = (const float*)d_in[4];
    const float* W1   = (const float*)d_in[5];
    const float* W2   = (const float*)d_in[6];
    const float* b2   = (const float*)d_in[7];

    xz_kernel<<<T_STEPS / TS, 256>>>(x, W_ih, b_ih, b_hh);
    scan_kernel<<<1, 128>>>(W_hh, W1, W2, b2, (float*)d_out);
}